// round 10
// baseline (speedup 1.0000x reference)
#include <cuda_runtime.h>

typedef unsigned long long ULL;

// ---------------- scratch (static device globals; no allocation) ----------------
__device__ float g_c1[128*32*55*55];    // conv1 out
__device__ float g_c2[128*64*26*26];    // conv2 out
__device__ float g_x [128*36954];       // conv3 out (flattened) + history
__device__ float g_part[145*16384];     // fc1 split-K partials
__device__ float g_h1[16384];           // h1 (128x128)
__device__ float g_w2t[128*256];        // w2 transposed (i-major)
__device__ float g_w3t[256*9];          // w3 transposed

// ---------------- packed f32x2 helpers ----------------
__device__ __forceinline__ void ffma2(ULL& c, ULL a, ULL b) {
    asm("fma.rn.f32x2 %0, %1, %2, %0;" : "+l"(c) : "l"(a), "l"(b));
}
__device__ __forceinline__ float lohi(ULL v) {
    float lo, hi;
    asm("mov.b64 {%0,%1}, %2;" : "=f"(lo), "=f"(hi) : "l"(v));
    return lo + hi;
}

// =================================================================
// conv1: (128,3,224,224) -> (128,32,55,55), 8x8 stride 4, relu
// block 128 thr: ocg=tid>>4 (8 groups x 4 oc), oxg=tid&15, ox=oxg+16m
// f32x2 packing over kx pairs (kx = 2p, 2p+1)
// =================================================================
__global__ __launch_bounds__(128, 4)
void conv1_kernel(const float* __restrict__ in, const float* __restrict__ w,
                  const float* __restrict__ bias) {
    __shared__ float2 ws[32*98];    // [oc][ic*8+ky][kxp]  (96 f2 per oc, pad 98)
    __shared__ float2 xs[24*114];   // [(ic*8+ky)][f2col], f2col = col/2, cols 0..227
    const int oy = blockIdx.x, b = blockIdx.y;
    const int tid = threadIdx.x;

    const float2* wg = (const float2*)w;
    for (int idx = tid; idx < 32*96; idx += 128) {
        int oc = idx / 96, r = idx % 96;
        ws[oc*98 + r] = wg[oc*96 + r];
    }
    const int iy0 = oy * 4;
    const float2* ing = (const float2*)(in + (long)b*3*224*224);
    for (int idx = tid; idx < 24*114; idx += 128) {
        int row = idx / 114, c2 = idx % 114;          // row = ic*8+ky
        int ic = row >> 3, ky = row & 7;
        float2 v = make_float2(0.f, 0.f);
        if (c2 < 112) v = ing[(ic*224 + iy0 + ky)*112 + c2];
        xs[row*114 + c2] = v;
    }
    __syncthreads();

    const int ocg = tid >> 4, oxg = tid & 15;
    int oxc2[4];
    #pragma unroll
    for (int m = 0; m < 4; ++m) {
        int ox = oxg + 16*m; if (ox > 55) ox = 55;   // clamp (garbage, discarded)
        oxc2[m] = ox * 2;
    }
    ULL acc[4][4];
    #pragma unroll
    for (int j = 0; j < 4; ++j)
        #pragma unroll
        for (int m = 0; m < 4; ++m) acc[j][m] = 0ULL;

    const ULL* ws_u = (const ULL*)ws;
    const ULL* xs_u = (const ULL*)xs;

    #pragma unroll
    for (int ic = 0; ic < 3; ++ic)
    #pragma unroll
    for (int ky = 0; ky < 8; ++ky) {
        const ULL* wr = ws_u + (ocg*4)*98 + (ic*8 + ky)*4;
        const ULL* xr = xs_u + (ic*8 + ky)*114;
        #pragma unroll
        for (int p = 0; p < 4; ++p) {
            ULL wv0 = wr[0*98 + p], wv1 = wr[1*98 + p], wv2 = wr[2*98 + p], wv3 = wr[3*98 + p];
            ULL xv0 = xr[oxc2[0] + p], xv1 = xr[oxc2[1] + p], xv2 = xr[oxc2[2] + p], xv3 = xr[oxc2[3] + p];
            ffma2(acc[0][0], wv0, xv0); ffma2(acc[0][1], wv0, xv1); ffma2(acc[0][2], wv0, xv2); ffma2(acc[0][3], wv0, xv3);
            ffma2(acc[1][0], wv1, xv0); ffma2(acc[1][1], wv1, xv1); ffma2(acc[1][2], wv1, xv2); ffma2(acc[1][3], wv1, xv3);
            ffma2(acc[2][0], wv2, xv0); ffma2(acc[2][1], wv2, xv1); ffma2(acc[2][2], wv2, xv2); ffma2(acc[2][3], wv2, xv3);
            ffma2(acc[3][0], wv3, xv0); ffma2(acc[3][1], wv3, xv1); ffma2(acc[3][2], wv3, xv2); ffma2(acc[3][3], wv3, xv3);
        }
    }
    #pragma unroll
    for (int j = 0; j < 4; ++j) {
        int oc = ocg*4 + j;
        float bv = bias[oc];
        #pragma unroll
        for (int m = 0; m < 4; ++m) {
            int ox = oxg + 16*m;
            if (ox < 55) {
                float r = lohi(acc[j][m]) + bv;
                g_c1[(((long)b*32 + oc)*55 + oy)*55 + ox] = fmaxf(r, 0.f);
            }
        }
    }
}

// =================================================================
// conv2: (128,32,55,55) -> (128,64,26,26), 4x4 stride 2, relu
// block 128: ocg=tid>>3 (16 x 4 oc), oxg=tid&7, ox=oxg+8m
// ic chunks of 8; f32x2 over kx pairs
// =================================================================
__global__ __launch_bounds__(128, 4)
void conv2_kernel(const float* __restrict__ w, const float* __restrict__ bias) {
    __shared__ float2 ws[64*66];     // [oc][(icl*4+ky)*2+p]  64 f2 per oc, pad 66
    __shared__ float2 xs[8*4*34];    // [(icl*4+ky)][f2col], cols 0..67
    const int oy = blockIdx.x, b = blockIdx.y;
    const int tid = threadIdx.x;
    const int ocg = tid >> 3, oxg = tid & 7;

    ULL acc[4][4];
    #pragma unroll
    for (int j = 0; j < 4; ++j)
        #pragma unroll
        for (int m = 0; m < 4; ++m) acc[j][m] = 0ULL;

    const float2* wg = (const float2*)w;
    const ULL* ws_u = (const ULL*)ws;
    const ULL* xs_u = (const ULL*)xs;

    for (int ci = 0; ci < 4; ++ci) {
        const int ic0 = ci * 8;
        __syncthreads();
        for (int idx = tid; idx < 64*64; idx += 128) {
            int oc = idx >> 6, r = idx & 63;
            ws[oc*66 + r] = wg[oc*256 + ic0*8 + r];
        }
        for (int idx = tid; idx < 8*4*68; idx += 128) {
            int icl = idx / 272, rem = idx % 272;
            int ky = rem / 68, col = rem % 68;
            int iy = oy*2 + ky;
            float v = 0.f;
            if (col < 55) v = g_c1[(((long)b*32 + ic0 + icl)*55 + iy)*55 + col];
            ((float*)xs)[(icl*4 + ky)*68 + col] = v;
        }
        __syncthreads();

        #pragma unroll
        for (int icl = 0; icl < 8; ++icl)
        #pragma unroll
        for (int ky = 0; ky < 4; ++ky) {
            const ULL* wr = ws_u + (ocg*4)*66 + (icl*4 + ky)*2;
            const ULL* xr = xs_u + (icl*4 + ky)*34;
            #pragma unroll
            for (int p = 0; p < 2; ++p) {
                ULL wv0 = wr[0*66 + p], wv1 = wr[1*66 + p], wv2 = wr[2*66 + p], wv3 = wr[3*66 + p];
                ULL xv0 = xr[oxg + 0 + p], xv1 = xr[oxg + 8 + p], xv2 = xr[oxg + 16 + p], xv3 = xr[oxg + 24 + p];
                ffma2(acc[0][0], wv0, xv0); ffma2(acc[0][1], wv0, xv1); ffma2(acc[0][2], wv0, xv2); ffma2(acc[0][3], wv0, xv3);
                ffma2(acc[1][0], wv1, xv0); ffma2(acc[1][1], wv1, xv1); ffma2(acc[1][2], wv1, xv2); ffma2(acc[1][3], wv1, xv3);
                ffma2(acc[2][0], wv2, xv0); ffma2(acc[2][1], wv2, xv1); ffma2(acc[2][2], wv2, xv2); ffma2(acc[2][3], wv2, xv3);
                ffma2(acc[3][0], wv3, xv0); ffma2(acc[3][1], wv3, xv1); ffma2(acc[3][2], wv3, xv2); ffma2(acc[3][3], wv3, xv3);
            }
        }
    }
    #pragma unroll
    for (int j = 0; j < 4; ++j) {
        int oc = ocg*4 + j;
        float bv = bias[oc];
        #pragma unroll
        for (int m = 0; m < 4; ++m) {
            int ox = oxg + 8*m;
            if (ox < 26) {
                float r = lohi(acc[j][m]) + bv;
                g_c2[(((long)b*64 + oc)*26 + oy)*26 + ox] = fmaxf(r, 0.f);
            }
        }
    }
}

// =================================================================
// conv3: (128,64,26,26) -> (128,64,24,24), 3x3 stride 1, relu
// block 128: ocg=tid>>3 (16 x 4 oc), oxg=tid&7, ox=oxg+8m (m<3, exact 24)
// ic-pair interleaved f32x2; ic chunks of 16 (8 pairs)
// writes flattened into g_x (c,y,x order)
// =================================================================
__global__ __launch_bounds__(128, 4)
void conv3_kernel(const float* __restrict__ w, const float* __restrict__ bias) {
    __shared__ float2 ws[64*74];   // [oc][icp*9 + ky*3 + kx] (72 f2 per oc, pad 74)
    __shared__ float2 xs[8*3*27];  // [(icp*3+ky)][col] cols 0..25, pad 27
    const int oy = blockIdx.x, b = blockIdx.y;
    const int tid = threadIdx.x;
    const int ocg = tid >> 3, oxg = tid & 7;

    ULL acc[4][3];
    #pragma unroll
    for (int j = 0; j < 4; ++j)
        #pragma unroll
        for (int m = 0; m < 3; ++m) acc[j][m] = 0ULL;

    const ULL* ws_u = (const ULL*)ws;
    const ULL* xs_u = (const ULL*)xs;

    for (int ci = 0; ci < 4; ++ci) {
        const int ic0 = ci * 16;
        __syncthreads();
        for (int idx = tid; idx < 64*72; idx += 128) {
            int oc = idx / 72, r = idx % 72;
            int icp = r / 9, k = r % 9;
            int gb = oc*576 + (ic0 + 2*icp)*9 + k;
            ws[oc*74 + r] = make_float2(w[gb], w[gb + 9]);
        }
        for (int idx = tid; idx < 8*3*26; idx += 128) {
            int icp = idx / 78, rem = idx % 78;
            int ky = rem / 26, col = rem % 26;
            int gb = (((b*64 + ic0 + 2*icp)*26) + oy + ky)*26 + col;
            xs[(icp*3 + ky)*27 + col] = make_float2(g_c2[gb], g_c2[gb + 676]);
        }
        __syncthreads();

        #pragma unroll
        for (int icp = 0; icp < 8; ++icp)
        #pragma unroll
        for (int ky = 0; ky < 3; ++ky) {
            const ULL* wr = ws_u + (ocg*4)*74 + icp*9 + ky*3;
            const ULL* xr = xs_u + (icp*3 + ky)*27;
            #pragma unroll
            for (int kx = 0; kx < 3; ++kx) {
                ULL wv0 = wr[0*74 + kx], wv1 = wr[1*74 + kx], wv2 = wr[2*74 + kx], wv3 = wr[3*74 + kx];
                ULL xv0 = xr[oxg + 0 + kx], xv1 = xr[oxg + 8 + kx], xv2 = xr[oxg + 16 + kx];
                ffma2(acc[0][0], wv0, xv0); ffma2(acc[0][1], wv0, xv1); ffma2(acc[0][2], wv0, xv2);
                ffma2(acc[1][0], wv1, xv0); ffma2(acc[1][1], wv1, xv1); ffma2(acc[1][2], wv1, xv2);
                ffma2(acc[2][0], wv2, xv0); ffma2(acc[2][1], wv2, xv1); ffma2(acc[2][2], wv2, xv2);
                ffma2(acc[3][0], wv3, xv0); ffma2(acc[3][1], wv3, xv1); ffma2(acc[3][2], wv3, xv2);
            }
        }
    }
    #pragma unroll
    for (int j = 0; j < 4; ++j) {
        int oc = ocg*4 + j;
        float bv = bias[oc];
        #pragma unroll
        for (int m = 0; m < 3; ++m) {
            int ox = oxg + 8*m;
            float r = lohi(acc[j][m]) + bv;
            g_x[(long)b*36954 + oc*576 + oy*24 + ox] = fmaxf(r, 0.f);
        }
    }
}

// =================================================================
// prep: transpose w2 / w3, copy history into g_x tail
// =================================================================
__global__ void prep_kernel(const float* __restrict__ w2, const float* __restrict__ w3,
                            const float* __restrict__ hist) {
    int idx = blockIdx.x*256 + threadIdx.x;   // grid 128 -> 32768
    if (idx < 32768) { int n = idx >> 7, i = idx & 127; g_w2t[i*256 + n] = w2[idx]; }
    if (idx < 2304)  { int j = idx >> 8, i = idx & 255; g_w3t[i*9 + j]  = w3[idx]; }
    if (idx < 128*90){ int b = idx / 90, t = idx % 90;  g_x[(long)b*36954 + 36864 + t] = hist[idx]; }
}

// =================================================================
// fc1 split-K partial GEMM: h1_part[blk] = x[:, k0:k0+256] @ w1[:, k0:k0+256].T
// grid 145, block 256 (16x16, 8x8 microtile)
// =================================================================
__global__ __launch_bounds__(256, 2)
void fc1_kernel(const float* __restrict__ w1) {
    __shared__ __align__(16) float As[16*132];
    __shared__ __align__(16) float Bs[16*132];
    const int blk = blockIdx.x;
    const int k0 = blk * 256;
    const int tid = threadIdx.x;
    const int tx = tid & 15, ty = tid >> 4;
    const int mrow = tid >> 1;
    const int khalf = (tid & 1) * 8;

    float c[8][8];
    #pragma unroll
    for (int i = 0; i < 8; ++i)
        #pragma unroll
        for (int j = 0; j < 8; ++j) c[i][j] = 0.f;

    for (int kt = 0; kt < 256; kt += 16) {
        #pragma unroll
        for (int i = 0; i < 8; ++i) {
            int kk = khalf + i;
            int k = k0 + kt + kk;
            float av = 0.f, bv = 0.f;
            if (k < 36954) {
                av = g_x[(long)mrow*36954 + k];
                bv = w1[(long)mrow*36954 + k];
            }
            As[kk*132 + mrow] = av;
            Bs[kk*132 + mrow] = bv;
        }
        __syncthreads();
        #pragma unroll
        for (int kk = 0; kk < 16; ++kk) {
            float4 a0 = *(const float4*)&As[kk*132 + ty*8];
            float4 a1 = *(const float4*)&As[kk*132 + ty*8 + 4];
            float4 b0 = *(const float4*)&Bs[kk*132 + tx*8];
            float4 b1 = *(const float4*)&Bs[kk*132 + tx*8 + 4];
            float a[8] = {a0.x,a0.y,a0.z,a0.w,a1.x,a1.y,a1.z,a1.w};
            float bb[8] = {b0.x,b0.y,b0.z,b0.w,b1.x,b1.y,b1.z,b1.w};
            #pragma unroll
            for (int i = 0; i < 8; ++i)
                #pragma unroll
                for (int j = 0; j < 8; ++j) c[i][j] += a[i]*bb[j];
        }
        __syncthreads();
    }
    #pragma unroll
    for (int i = 0; i < 8; ++i)
        #pragma unroll
        for (int j = 0; j < 8; ++j)
            g_part[(long)blk*16384 + (ty*8 + i)*128 + (tx*8 + j)] = c[i][j];
}

__global__ void fc1_reduce(const float* __restrict__ b1) {
    int e = blockIdx.x*512 + threadIdx.x;   // grid 32
    float s = b1[e & 127];
    #pragma unroll 4
    for (int p = 0; p < 145; ++p) s += g_part[(long)p*16384 + e];
    g_h1[e] = s;
}

// =================================================================
// LIF scan: one block per sample, 256 threads, T=10
// =================================================================
__global__ __launch_bounds__(256, 1)
void scan_kernel(const float* __restrict__ b2, const float* __restrict__ b3,
                 float* __restrict__ out) {
    __shared__ float h1s[128], spk1[128], spk2[256], p3[9*17];
    const int b = blockIdx.x, t = threadIdx.x;
    if (t < 128) h1s[t] = g_h1[b*128 + t];
    float mem1 = 0.f, syn1 = 0.f, mem2 = 0.f, syn2 = 0.f;
    float mem3 = 0.f, syn3 = 0.f, pot = 0.f;
    const float b2r = b2[t];
    __syncthreads();

    for (int step = 0; step < 10; ++step) {
        if (t < 128) {
            syn1 = 0.9f*syn1 + h1s[t];
            mem1 = 0.8f*mem1 + syn1;
            float s = (mem1 > 1.0f) ? 1.0f : 0.0f;
            mem1 -= s;
            spk1[t] = s;
        }
        __syncthreads();
        float h2 = b2r;
        const float* w2c = g_w2t + t;
        #pragma unroll 8
        for (int i = 0; i < 128; ++i) h2 += spk1[i] * w2c[i*256];
        syn2 = 0.9f*syn2 + h2;
        mem2 = 0.8f*mem2 + syn2;
        float s2 = (mem2 > 1.0f) ? 1.0f : 0.0f;
        mem2 -= s2;
        spk2[t] = s2;
        __syncthreads();
        if (t < 144) {
            int j = t >> 4, seg = t & 15;
            float p = 0.f;
            const float* w3c = g_w3t + j;
            #pragma unroll
            for (int i = 0; i < 16; ++i) p += spk2[seg*16 + i] * w3c[(seg*16 + i)*9];
            p3[j*17 + seg] = p;
        }
        __syncthreads();
        if (t < 9) {
            float h3 = b3[t];
            #pragma unroll
            for (int s = 0; s < 16; ++s) h3 += p3[t*17 + s];
            syn3 = 0.9f*syn3 + h3;
            mem3 = 0.8f*mem3 + syn3;
            pot += mem3;
        }
        __syncthreads();
    }
    if (t < 9) out[b*9 + t] = pot * 0.1f;
}

// =================================================================
extern "C" void kernel_launch(void* const* d_in, const int* in_sizes, int n_in,
                              void* d_out, int out_size) {
    const float* state   = (const float*)d_in[0];
    const float* history = (const float*)d_in[1];
    const float* cw1 = (const float*)d_in[2];
    const float* cb1 = (const float*)d_in[3];
    const float* cw2 = (const float*)d_in[4];
    const float* cb2 = (const float*)d_in[5];
    const float* cw3 = (const float*)d_in[6];
    const float* cb3 = (const float*)d_in[7];
    const float* w1  = (const float*)d_in[8];
    const float* b1  = (const float*)d_in[9];
    const float* w2  = (const float*)d_in[10];
    const float* b2  = (const float*)d_in[11];
    const float* w3  = (const float*)d_in[12];
    const float* b3  = (const float*)d_in[13];
    float* out = (float*)d_out;

    prep_kernel<<<128, 256>>>(w2, w3, history);
    conv1_kernel<<<dim3(55, 128), 128>>>(state, cw1, cb1);
    conv2_kernel<<<dim3(26, 128), 128>>>(cw2, cb2);
    conv3_kernel<<<dim3(24, 128), 128>>>(cw3, cb3);
    fc1_kernel<<<145, 256>>>(w1);
    fc1_reduce<<<32, 512>>>(b1);
    scan_kernel<<<128, 256>>>(b2, b3, out);
}

// round 11
// speedup vs baseline: 1.0899x; 1.0899x over previous
#include <cuda_runtime.h>

typedef unsigned long long ULL;

// ---------------- scratch (static device globals; no allocation) ----------------
__device__ float g_c1[128*32*55*55];    // conv1 out
__device__ float g_c2[128*64*26*26];    // conv2 out
__device__ float g_x [128*36954];       // conv3 out (flattened) + history
__device__ float g_part[145*16384];     // fc1 split-K partials
__device__ float g_h1[16384];           // h1 (128x128)
__device__ float g_w2t[128*256];        // w2 transposed (i-major)
__device__ float g_w3t[256*9];          // w3 transposed

// ---------------- packed f32x2 helpers ----------------
__device__ __forceinline__ void ffma2(ULL& c, ULL a, ULL b) {
    asm("fma.rn.f32x2 %0, %1, %2, %0;" : "+l"(c) : "l"(a), "l"(b));
}
__device__ __forceinline__ float lohi(ULL v) {
    float lo, hi;
    asm("mov.b64 {%0,%1}, %2;" : "=f"(lo), "=f"(hi) : "l"(v));
    return lo + hi;
}

// =================================================================
// conv1: (128,3,224,224) -> (128,32,55,55), 8x8 stride 4, relu
// (unchanged from R10 passing version — correctness anchor)
// =================================================================
__global__ __launch_bounds__(128, 4)
void conv1_kernel(const float* __restrict__ in, const float* __restrict__ w,
                  const float* __restrict__ bias) {
    __shared__ float2 ws[32*98];
    __shared__ float2 xs[24*114];
    const int oy = blockIdx.x, b = blockIdx.y;
    const int tid = threadIdx.x;

    const float2* wg = (const float2*)w;
    for (int idx = tid; idx < 32*96; idx += 128) {
        int oc = idx / 96, r = idx % 96;
        ws[oc*98 + r] = wg[oc*96 + r];
    }
    const int iy0 = oy * 4;
    const float2* ing = (const float2*)(in + (long)b*3*224*224);
    for (int idx = tid; idx < 24*114; idx += 128) {
        int row = idx / 114, c2 = idx % 114;
        int ic = row >> 3, ky = row & 7;
        float2 v = make_float2(0.f, 0.f);
        if (c2 < 112) v = ing[(ic*224 + iy0 + ky)*112 + c2];
        xs[row*114 + c2] = v;
    }
    __syncthreads();

    const int ocg = tid >> 4, oxg = tid & 15;
    int oxc2[4];
    #pragma unroll
    for (int m = 0; m < 4; ++m) {
        int ox = oxg + 16*m; if (ox > 55) ox = 55;
        oxc2[m] = ox * 2;
    }
    ULL acc[4][4];
    #pragma unroll
    for (int j = 0; j < 4; ++j)
        #pragma unroll
        for (int m = 0; m < 4; ++m) acc[j][m] = 0ULL;

    const ULL* ws_u = (const ULL*)ws;
    const ULL* xs_u = (const ULL*)xs;

    #pragma unroll
    for (int ic = 0; ic < 3; ++ic)
    #pragma unroll
    for (int ky = 0; ky < 8; ++ky) {
        const ULL* wr = ws_u + (ocg*4)*98 + (ic*8 + ky)*4;
        const ULL* xr = xs_u + (ic*8 + ky)*114;
        #pragma unroll
        for (int p = 0; p < 4; ++p) {
            ULL wv0 = wr[0*98 + p], wv1 = wr[1*98 + p], wv2 = wr[2*98 + p], wv3 = wr[3*98 + p];
            ULL xv0 = xr[oxc2[0] + p], xv1 = xr[oxc2[1] + p], xv2 = xr[oxc2[2] + p], xv3 = xr[oxc2[3] + p];
            ffma2(acc[0][0], wv0, xv0); ffma2(acc[0][1], wv0, xv1); ffma2(acc[0][2], wv0, xv2); ffma2(acc[0][3], wv0, xv3);
            ffma2(acc[1][0], wv1, xv0); ffma2(acc[1][1], wv1, xv1); ffma2(acc[1][2], wv1, xv2); ffma2(acc[1][3], wv1, xv3);
            ffma2(acc[2][0], wv2, xv0); ffma2(acc[2][1], wv2, xv1); ffma2(acc[2][2], wv2, xv2); ffma2(acc[2][3], wv2, xv3);
            ffma2(acc[3][0], wv3, xv0); ffma2(acc[3][1], wv3, xv1); ffma2(acc[3][2], wv3, xv2); ffma2(acc[3][3], wv3, xv3);
        }
    }
    #pragma unroll
    for (int j = 0; j < 4; ++j) {
        int oc = ocg*4 + j;
        float bv = bias[oc];
        #pragma unroll
        for (int m = 0; m < 4; ++m) {
            int ox = oxg + 16*m;
            if (ox < 55) {
                float r = lohi(acc[j][m]) + bv;
                g_c1[(((long)b*32 + oc)*55 + oy)*55 + ox] = fmaxf(r, 0.f);
            }
        }
    }
}

// =================================================================
// conv2 v2: (128,32,55,55) -> (128,64,26,26), 4x4 stride 2, relu
// 256 thr: warp = ocg (8 oc, broadcast w), lane: slab=lane>>3 (4 out rows),
// oxg=lane&7 (ox = oxg+8m, m<4). ic chunks of 4; f32x2 over kx pairs.
// Block covers 4 output rows x 64 oc. grid (7, 128).
// =================================================================
__global__ __launch_bounds__(256, 2)
void conv2_kernel(const float* __restrict__ w, const float* __restrict__ bias) {
    __shared__ float2 ws[64*33];     // [oc][icl*8 + ky*2 + p], icl<4, pad 33 (16896 B)
    __shared__ float  xs[4*10*68];   // [icl][row 10][col 68] (10880 B)
    const int oyp = blockIdx.x, b = blockIdx.y;
    const int oy0 = oyp * 4;
    const int tid = threadIdx.x;
    const int ocg  = tid >> 5;        // warp id: 8 oc per warp
    const int lane = tid & 31;
    const int slab = lane >> 3;       // output row within block
    const int oxg  = lane & 7;
    const int oy   = oy0 + slab;

    ULL acc[8][4];
    #pragma unroll
    for (int j = 0; j < 8; ++j)
        #pragma unroll
        for (int m = 0; m < 4; ++m) acc[j][m] = 0ULL;

    const float2* wg = (const float2*)w;
    const ULL* ws_u = (const ULL*)ws;
    const ULL* xs_u = (const ULL*)xs;

    for (int ci = 0; ci < 8; ++ci) {
        const int ic0 = ci * 4;
        __syncthreads();
        for (int idx = tid; idx < 64*32; idx += 256) {
            int oc = idx >> 5, r = idx & 31;        // r = icl*8 + ky*2 + p
            ws[oc*33 + r] = wg[oc*256 + ic0*8 + r];
        }
        for (int idx = tid; idx < 4*10*68; idx += 256) {
            int icl = idx / 680, rem = idx % 680;
            int row = rem / 68, col = rem % 68;
            int iy = oy0*2 + row;
            float v = 0.f;
            if (col < 55 && iy < 55)
                v = g_c1[(((long)b*32 + ic0 + icl)*55 + iy)*55 + col];
            xs[(icl*10 + row)*68 + col] = v;
        }
        __syncthreads();

        #pragma unroll
        for (int icl = 0; icl < 4; ++icl)
        #pragma unroll
        for (int ky = 0; ky < 4; ++ky) {
            const ULL* wr = ws_u + (ocg*8)*33 + icl*8 + ky*2;
            const ULL* xr = xs_u + (icl*10 + 2*slab + ky)*34;
            #pragma unroll
            for (int p = 0; p < 2; ++p) {
                ULL wv0 = wr[0*33+p], wv1 = wr[1*33+p], wv2 = wr[2*33+p], wv3 = wr[3*33+p];
                ULL wv4 = wr[4*33+p], wv5 = wr[5*33+p], wv6 = wr[6*33+p], wv7 = wr[7*33+p];
                ULL xv0 = xr[oxg + 0 + p], xv1 = xr[oxg + 8 + p];
                ULL xv2 = xr[oxg + 16 + p], xv3 = xr[oxg + 24 + p];
                ffma2(acc[0][0], wv0, xv0); ffma2(acc[0][1], wv0, xv1); ffma2(acc[0][2], wv0, xv2); ffma2(acc[0][3], wv0, xv3);
                ffma2(acc[1][0], wv1, xv0); ffma2(acc[1][1], wv1, xv1); ffma2(acc[1][2], wv1, xv2); ffma2(acc[1][3], wv1, xv3);
                ffma2(acc[2][0], wv2, xv0); ffma2(acc[2][1], wv2, xv1); ffma2(acc[2][2], wv2, xv2); ffma2(acc[2][3], wv2, xv3);
                ffma2(acc[3][0], wv3, xv0); ffma2(acc[3][1], wv3, xv1); ffma2(acc[3][2], wv3, xv2); ffma2(acc[3][3], wv3, xv3);
                ffma2(acc[4][0], wv4, xv0); ffma2(acc[4][1], wv4, xv1); ffma2(acc[4][2], wv4, xv2); ffma2(acc[4][3], wv4, xv3);
                ffma2(acc[5][0], wv5, xv0); ffma2(acc[5][1], wv5, xv1); ffma2(acc[5][2], wv5, xv2); ffma2(acc[5][3], wv5, xv3);
                ffma2(acc[6][0], wv6, xv0); ffma2(acc[6][1], wv6, xv1); ffma2(acc[6][2], wv6, xv2); ffma2(acc[6][3], wv6, xv3);
                ffma2(acc[7][0], wv7, xv0); ffma2(acc[7][1], wv7, xv1); ffma2(acc[7][2], wv7, xv2); ffma2(acc[7][3], wv7, xv3);
            }
        }
    }
    if (oy < 26) {
        #pragma unroll
        for (int j = 0; j < 8; ++j) {
            int oc = ocg*8 + j;
            float bv = bias[oc];
            #pragma unroll
            for (int m = 0; m < 4; ++m) {
                int ox = oxg + 8*m;
                if (ox < 26) {
                    float r = lohi(acc[j][m]) + bv;
                    g_c2[(((long)b*64 + oc)*26 + oy)*26 + ox] = fmaxf(r, 0.f);
                }
            }
        }
    }
}

// =================================================================
// conv3 v2: (128,64,26,26) -> (128,64,24,24), 3x3 stride 1, relu
// 256 thr: warp = ocg (8 oc, broadcast w), lane: slab=lane>>3 (4 out rows),
// oxg=lane&7 (ox = oxg+8m, m<3, exact 24). ic-pair f32x2, chunks of 16.
// Block covers 4 output rows x 64 oc. grid (6, 128). xs pad 28 -> 2-phase LDS.
// =================================================================
__global__ __launch_bounds__(256, 2)
void conv3_kernel(const float* __restrict__ w, const float* __restrict__ bias) {
    __shared__ float2 ws[64*74];     // [oc][icp*9 + ky*3 + kx], pad 74 (37888 B)
    __shared__ float2 xs[8*6*28];    // [icp][row 6][col 26, pad 28] (10752 B)
    const int oyp = blockIdx.x, b = blockIdx.y;
    const int oy0 = oyp * 4;
    const int tid = threadIdx.x;
    const int ocg  = tid >> 5;        // warp id: 8 oc per warp
    const int lane = tid & 31;
    const int slab = lane >> 3;       // output row within block
    const int oxg  = lane & 7;
    const int oy   = oy0 + slab;

    ULL acc[8][3];
    #pragma unroll
    for (int j = 0; j < 8; ++j)
        #pragma unroll
        for (int m = 0; m < 3; ++m) acc[j][m] = 0ULL;

    const ULL* ws_u = (const ULL*)ws;
    const ULL* xs_u = (const ULL*)xs;

    for (int ci = 0; ci < 4; ++ci) {
        const int ic0 = ci * 16;
        __syncthreads();
        for (int idx = tid; idx < 64*72; idx += 256) {
            int oc = idx / 72, r = idx % 72;
            int icp = r / 9, k = r % 9;
            int gb = oc*576 + (ic0 + 2*icp)*9 + k;
            ws[oc*74 + r] = make_float2(w[gb], w[gb + 9]);
        }
        for (int idx = tid; idx < 8*6*26; idx += 256) {
            int icp = idx / 156, rem = idx % 156;
            int row = rem / 26, col = rem % 26;
            int iy = oy0 + row;                 // oy0<=20 -> iy<=25, always valid
            int gb = (((b*64 + ic0 + 2*icp)*26) + iy)*26 + col;
            xs[(icp*6 + row)*28 + col] = make_float2(g_c2[gb], g_c2[gb + 676]);
        }
        __syncthreads();

        #pragma unroll
        for (int icp = 0; icp < 8; ++icp)
        #pragma unroll
        for (int ky = 0; ky < 3; ++ky) {
            const ULL* wr = ws_u + (ocg*8)*74 + icp*9 + ky*3;
            const ULL* xr = xs_u + (icp*6 + slab + ky)*28;
            #pragma unroll
            for (int kx = 0; kx < 3; ++kx) {
                ULL wv0 = wr[0*74+kx], wv1 = wr[1*74+kx], wv2 = wr[2*74+kx], wv3 = wr[3*74+kx];
                ULL wv4 = wr[4*74+kx], wv5 = wr[5*74+kx], wv6 = wr[6*74+kx], wv7 = wr[7*74+kx];
                ULL xv0 = xr[oxg + 0 + kx], xv1 = xr[oxg + 8 + kx], xv2 = xr[oxg + 16 + kx];
                ffma2(acc[0][0], wv0, xv0); ffma2(acc[0][1], wv0, xv1); ffma2(acc[0][2], wv0, xv2);
                ffma2(acc[1][0], wv1, xv0); ffma2(acc[1][1], wv1, xv1); ffma2(acc[1][2], wv1, xv2);
                ffma2(acc[2][0], wv2, xv0); ffma2(acc[2][1], wv2, xv1); ffma2(acc[2][2], wv2, xv2);
                ffma2(acc[3][0], wv3, xv0); ffma2(acc[3][1], wv3, xv1); ffma2(acc[3][2], wv3, xv2);
                ffma2(acc[4][0], wv4, xv0); ffma2(acc[4][1], wv4, xv1); ffma2(acc[4][2], wv4, xv2);
                ffma2(acc[5][0], wv5, xv0); ffma2(acc[5][1], wv5, xv1); ffma2(acc[5][2], wv5, xv2);
                ffma2(acc[6][0], wv6, xv0); ffma2(acc[6][1], wv6, xv1); ffma2(acc[6][2], wv6, xv2);
                ffma2(acc[7][0], wv7, xv0); ffma2(acc[7][1], wv7, xv1); ffma2(acc[7][2], wv7, xv2);
            }
        }
    }
    #pragma unroll
    for (int j = 0; j < 8; ++j) {
        int oc = ocg*8 + j;
        float bv = bias[oc];
        #pragma unroll
        for (int m = 0; m < 3; ++m) {
            int ox = oxg + 8*m;
            float r = lohi(acc[j][m]) + bv;
            g_x[(long)b*36954 + oc*576 + oy*24 + ox] = fmaxf(r, 0.f);
        }
    }
}

// =================================================================
// prep: transpose w2 / w3, copy history into g_x tail
// =================================================================
__global__ void prep_kernel(const float* __restrict__ w2, const float* __restrict__ w3,
                            const float* __restrict__ hist) {
    int idx = blockIdx.x*256 + threadIdx.x;   // grid 128 -> 32768
    if (idx < 32768) { int n = idx >> 7, i = idx & 127; g_w2t[i*256 + n] = w2[idx]; }
    if (idx < 2304)  { int j = idx >> 8, i = idx & 255; g_w3t[i*9 + j]  = w3[idx]; }
    if (idx < 128*90){ int b = idx / 90, t = idx % 90;  g_x[(long)b*36954 + 36864 + t] = hist[idx]; }
}

// =================================================================
// fc1 split-K partial GEMM: h1_part[blk] = x[:, k0:k0+256] @ w1[:, k0:k0+256].T
// =================================================================
__global__ __launch_bounds__(256, 2)
void fc1_kernel(const float* __restrict__ w1) {
    __shared__ __align__(16) float As[16*132];
    __shared__ __align__(16) float Bs[16*132];
    const int blk = blockIdx.x;
    const int k0 = blk * 256;
    const int tid = threadIdx.x;
    const int tx = tid & 15, ty = tid >> 4;
    const int mrow = tid >> 1;
    const int khalf = (tid & 1) * 8;

    float c[8][8];
    #pragma unroll
    for (int i = 0; i < 8; ++i)
        #pragma unroll
        for (int j = 0; j < 8; ++j) c[i][j] = 0.f;

    for (int kt = 0; kt < 256; kt += 16) {
        #pragma unroll
        for (int i = 0; i < 8; ++i) {
            int kk = khalf + i;
            int k = k0 + kt + kk;
            float av = 0.f, bv = 0.f;
            if (k < 36954) {
                av = g_x[(long)mrow*36954 + k];
                bv = w1[(long)mrow*36954 + k];
            }
            As[kk*132 + mrow] = av;
            Bs[kk*132 + mrow] = bv;
        }
        __syncthreads();
        #pragma unroll
        for (int kk = 0; kk < 16; ++kk) {
            float4 a0 = *(const float4*)&As[kk*132 + ty*8];
            float4 a1 = *(const float4*)&As[kk*132 + ty*8 + 4];
            float4 b0 = *(const float4*)&Bs[kk*132 + tx*8];
            float4 b1 = *(const float4*)&Bs[kk*132 + tx*8 + 4];
            float a[8] = {a0.x,a0.y,a0.z,a0.w,a1.x,a1.y,a1.z,a1.w};
            float bb[8] = {b0.x,b0.y,b0.z,b0.w,b1.x,b1.y,b1.z,b1.w};
            #pragma unroll
            for (int i = 0; i < 8; ++i)
                #pragma unroll
                for (int j = 0; j < 8; ++j) c[i][j] += a[i]*bb[j];
        }
        __syncthreads();
    }
    #pragma unroll
    for (int i = 0; i < 8; ++i)
        #pragma unroll
        for (int j = 0; j < 8; ++j)
            g_part[(long)blk*16384 + (ty*8 + i)*128 + (tx*8 + j)] = c[i][j];
}

__global__ void fc1_reduce(const float* __restrict__ b1) {
    int e = blockIdx.x*512 + threadIdx.x;   // grid 32
    float s = b1[e & 127];
    #pragma unroll 4
    for (int p = 0; p < 145; ++p) s += g_part[(long)p*16384 + e];
    g_h1[e] = s;
}

// =================================================================
// LIF scan: one block per sample, 256 threads, T=10
// =================================================================
__global__ __launch_bounds__(256, 1)
void scan_kernel(const float* __restrict__ b2, const float* __restrict__ b3,
                 float* __restrict__ out) {
    __shared__ float h1s[128], spk1[128], spk2[256], p3[9*17];
    const int b = blockIdx.x, t = threadIdx.x;
    if (t < 128) h1s[t] = g_h1[b*128 + t];
    float mem1 = 0.f, syn1 = 0.f, mem2 = 0.f, syn2 = 0.f;
    float mem3 = 0.f, syn3 = 0.f, pot = 0.f;
    const float b2r = b2[t];
    __syncthreads();

    for (int step = 0; step < 10; ++step) {
        if (t < 128) {
            syn1 = 0.9f*syn1 + h1s[t];
            mem1 = 0.8f*mem1 + syn1;
            float s = (mem1 > 1.0f) ? 1.0f : 0.0f;
            mem1 -= s;
            spk1[t] = s;
        }
        __syncthreads();
        float h2 = b2r;
        const float* w2c = g_w2t + t;
        #pragma unroll 8
        for (int i = 0; i < 128; ++i) h2 += spk1[i] * w2c[i*256];
        syn2 = 0.9f*syn2 + h2;
        mem2 = 0.8f*mem2 + syn2;
        float s2 = (mem2 > 1.0f) ? 1.0f : 0.0f;
        mem2 -= s2;
        spk2[t] = s2;
        __syncthreads();
        if (t < 144) {
            int j = t >> 4, seg = t & 15;
            float p = 0.f;
            const float* w3c = g_w3t + j;
            #pragma unroll
            for (int i = 0; i < 16; ++i) p += spk2[seg*16 + i] * w3c[(seg*16 + i)*9];
            p3[j*17 + seg] = p;
        }
        __syncthreads();
        if (t < 9) {
            float h3 = b3[t];
            #pragma unroll
            for (int s = 0; s < 16; ++s) h3 += p3[t*17 + s];
            syn3 = 0.9f*syn3 + h3;
            mem3 = 0.8f*mem3 + syn3;
            pot += mem3;
        }
        __syncthreads();
    }
    if (t < 9) out[b*9 + t] = pot * 0.1f;
}

// =================================================================
extern "C" void kernel_launch(void* const* d_in, const int* in_sizes, int n_in,
                              void* d_out, int out_size) {
    const float* state   = (const float*)d_in[0];
    const float* history = (const float*)d_in[1];
    const float* cw1 = (const float*)d_in[2];
    const float* cb1 = (const float*)d_in[3];
    const float* cw2 = (const float*)d_in[4];
    const float* cb2 = (const float*)d_in[5];
    const float* cw3 = (const float*)d_in[6];
    const float* cb3 = (const float*)d_in[7];
    const float* w1  = (const float*)d_in[8];
    const float* b1  = (const float*)d_in[9];
    const float* w2  = (const float*)d_in[10];
    const float* b2  = (const float*)d_in[11];
    const float* w3  = (const float*)d_in[12];
    const float* b3  = (const float*)d_in[13];
    float* out = (float*)d_out;

    prep_kernel<<<128, 256>>>(w2, w3, history);
    conv1_kernel<<<dim3(55, 128), 128>>>(state, cw1, cb1);
    conv2_kernel<<<dim3(7, 128), 256>>>(cw2, cb2);
    conv3_kernel<<<dim3(6, 128), 256>>>(cw3, cb3);
    fc1_kernel<<<145, 256>>>(w1);
    fc1_reduce<<<32, 512>>>(b1);
    scan_kernel<<<128, 256>>>(b2, b3, out);
}

// round 14
// speedup vs baseline: 1.1204x; 1.0280x over previous
#include <cuda_runtime.h>

typedef unsigned long long ULL;

// ---------------- scratch (static device globals; no allocation) ----------------
__device__ float g_c1[128*32*55*55];    // conv1 out
__device__ float g_c2[128*64*26*26];    // conv2 out
__device__ float g_x [128*36954];       // conv3 out (flattened) + history
__device__ float g_part[145*16384];     // fc1 split-K partials
__device__ float g_h1[16384];           // h1 (128x128)
__device__ float g_w2t[128*256];        // w2 transposed (i-major)
__device__ float g_w3t[256*9];          // w3 transposed

// ---------------- packed f32x2 helpers ----------------
__device__ __forceinline__ void ffma2(ULL& c, ULL a, ULL b) {
    asm("fma.rn.f32x2 %0, %1, %2, %0;" : "+l"(c) : "l"(a), "l"(b));
}
__device__ __forceinline__ float lohi(ULL v) {
    float lo, hi;
    asm("mov.b64 {%0,%1}, %2;" : "=f"(lo), "=f"(hi) : "l"(v));
    return lo + hi;
}

// =================================================================
// conv1: (128,3,224,224) -> (128,32,55,55), 8x8 stride 4, relu (unchanged)
// =================================================================
__global__ __launch_bounds__(128, 4)
void conv1_kernel(const float* __restrict__ in, const float* __restrict__ w,
                  const float* __restrict__ bias) {
    __shared__ float2 ws[32*98];
    __shared__ float2 xs[24*114];
    const int oy = blockIdx.x, b = blockIdx.y;
    const int tid = threadIdx.x;

    const float2* wg = (const float2*)w;
    for (int idx = tid; idx < 32*96; idx += 128) {
        int oc = idx / 96, r = idx % 96;
        ws[oc*98 + r] = wg[oc*96 + r];
    }
    const int iy0 = oy * 4;
    const float2* ing = (const float2*)(in + (long)b*3*224*224);
    for (int idx = tid; idx < 24*114; idx += 128) {
        int row = idx / 114, c2 = idx % 114;
        int ic = row >> 3, ky = row & 7;
        float2 v = make_float2(0.f, 0.f);
        if (c2 < 112) v = ing[(ic*224 + iy0 + ky)*112 + c2];
        xs[row*114 + c2] = v;
    }
    __syncthreads();

    const int ocg = tid >> 4, oxg = tid & 15;
    int oxc2[4];
    #pragma unroll
    for (int m = 0; m < 4; ++m) {
        int ox = oxg + 16*m; if (ox > 55) ox = 55;
        oxc2[m] = ox * 2;
    }
    ULL acc[4][4];
    #pragma unroll
    for (int j = 0; j < 4; ++j)
        #pragma unroll
        for (int m = 0; m < 4; ++m) acc[j][m] = 0ULL;

    const ULL* ws_u = (const ULL*)ws;
    const ULL* xs_u = (const ULL*)xs;

    #pragma unroll
    for (int ic = 0; ic < 3; ++ic)
    #pragma unroll
    for (int ky = 0; ky < 8; ++ky) {
        const ULL* wr = ws_u + (ocg*4)*98 + (ic*8 + ky)*4;
        const ULL* xr = xs_u + (ic*8 + ky)*114;
        #pragma unroll
        for (int p = 0; p < 4; ++p) {
            ULL wv0 = wr[0*98 + p], wv1 = wr[1*98 + p], wv2 = wr[2*98 + p], wv3 = wr[3*98 + p];
            ULL xv0 = xr[oxc2[0] + p], xv1 = xr[oxc2[1] + p], xv2 = xr[oxc2[2] + p], xv3 = xr[oxc2[3] + p];
            ffma2(acc[0][0], wv0, xv0); ffma2(acc[0][1], wv0, xv1); ffma2(acc[0][2], wv0, xv2); ffma2(acc[0][3], wv0, xv3);
            ffma2(acc[1][0], wv1, xv0); ffma2(acc[1][1], wv1, xv1); ffma2(acc[1][2], wv1, xv2); ffma2(acc[1][3], wv1, xv3);
            ffma2(acc[2][0], wv2, xv0); ffma2(acc[2][1], wv2, xv1); ffma2(acc[2][2], wv2, xv2); ffma2(acc[2][3], wv2, xv3);
            ffma2(acc[3][0], wv3, xv0); ffma2(acc[3][1], wv3, xv1); ffma2(acc[3][2], wv3, xv2); ffma2(acc[3][3], wv3, xv3);
        }
    }
    #pragma unroll
    for (int j = 0; j < 4; ++j) {
        int oc = ocg*4 + j;
        float bv = bias[oc];
        #pragma unroll
        for (int m = 0; m < 4; ++m) {
            int ox = oxg + 16*m;
            if (ox < 55) {
                float r = lohi(acc[j][m]) + bv;
                g_c1[(((long)b*32 + oc)*55 + oy)*55 + ox] = fmaxf(r, 0.f);
            }
        }
    }
}

// =================================================================
// conv2 v3: xs row padded to 72 floats so the 4-slab LDS.64 pattern is
// exactly 2 crossbar phases (2-row stride = 144 words = 16 mod 32).
// =================================================================
__global__ __launch_bounds__(256, 2)
void conv2_kernel(const float* __restrict__ w, const float* __restrict__ bias) {
    __shared__ float2 ws[64*33];     // [oc][icl*8 + ky*2 + p], icl<4 (16896 B)
    __shared__ float  xs[4*10*72];   // [icl][row 10][col 72] (11520 B)
    const int oyp = blockIdx.x, b = blockIdx.y;
    const int oy0 = oyp * 4;
    const int tid = threadIdx.x;
    const int ocg  = tid >> 5;
    const int lane = tid & 31;
    const int slab = lane >> 3;
    const int oxg  = lane & 7;
    const int oy   = oy0 + slab;

    ULL acc[8][4];
    #pragma unroll
    for (int j = 0; j < 8; ++j)
        #pragma unroll
        for (int m = 0; m < 4; ++m) acc[j][m] = 0ULL;

    const float2* wg = (const float2*)w;
    const ULL* ws_u = (const ULL*)ws;
    const ULL* xs_u = (const ULL*)xs;

    for (int ci = 0; ci < 8; ++ci) {
        const int ic0 = ci * 4;
        __syncthreads();
        for (int idx = tid; idx < 64*32; idx += 256) {
            int oc = idx >> 5, r = idx & 31;
            ws[oc*33 + r] = wg[oc*256 + ic0*8 + r];
        }
        for (int idx = tid; idx < 4*10*68; idx += 256) {
            int icl = idx / 680, rem = idx % 680;
            int row = rem / 68, col = rem % 68;
            int iy = oy0*2 + row;
            float v = 0.f;
            if (col < 55 && iy < 55)
                v = g_c1[(((long)b*32 + ic0 + icl)*55 + iy)*55 + col];
            xs[(icl*10 + row)*72 + col] = v;
        }
        __syncthreads();

        #pragma unroll
        for (int icl = 0; icl < 4; ++icl)
        #pragma unroll
        for (int ky = 0; ky < 4; ++ky) {
            const ULL* wr = ws_u + (ocg*8)*33 + icl*8 + ky*2;
            const ULL* xr = xs_u + (icl*10 + 2*slab + ky)*36;
            #pragma unroll
            for (int p = 0; p < 2; ++p) {
                ULL wv0 = wr[0*33+p], wv1 = wr[1*33+p], wv2 = wr[2*33+p], wv3 = wr[3*33+p];
                ULL wv4 = wr[4*33+p], wv5 = wr[5*33+p], wv6 = wr[6*33+p], wv7 = wr[7*33+p];
                ULL xv0 = xr[oxg + 0 + p], xv1 = xr[oxg + 8 + p];
                ULL xv2 = xr[oxg + 16 + p], xv3 = xr[oxg + 24 + p];
                ffma2(acc[0][0], wv0, xv0); ffma2(acc[0][1], wv0, xv1); ffma2(acc[0][2], wv0, xv2); ffma2(acc[0][3], wv0, xv3);
                ffma2(acc[1][0], wv1, xv0); ffma2(acc[1][1], wv1, xv1); ffma2(acc[1][2], wv1, xv2); ffma2(acc[1][3], wv1, xv3);
                ffma2(acc[2][0], wv2, xv0); ffma2(acc[2][1], wv2, xv1); ffma2(acc[2][2], wv2, xv2); ffma2(acc[2][3], wv2, xv3);
                ffma2(acc[3][0], wv3, xv0); ffma2(acc[3][1], wv3, xv1); ffma2(acc[3][2], wv3, xv2); ffma2(acc[3][3], wv3, xv3);
                ffma2(acc[4][0], wv4, xv0); ffma2(acc[4][1], wv4, xv1); ffma2(acc[4][2], wv4, xv2); ffma2(acc[4][3], wv4, xv3);
                ffma2(acc[5][0], wv5, xv0); ffma2(acc[5][1], wv5, xv1); ffma2(acc[5][2], wv5, xv2); ffma2(acc[5][3], wv5, xv3);
                ffma2(acc[6][0], wv6, xv0); ffma2(acc[6][1], wv6, xv1); ffma2(acc[6][2], wv6, xv2); ffma2(acc[6][3], wv6, xv3);
                ffma2(acc[7][0], wv7, xv0); ffma2(acc[7][1], wv7, xv1); ffma2(acc[7][2], wv7, xv2); ffma2(acc[7][3], wv7, xv3);
            }
        }
    }
    if (oy < 26) {
        #pragma unroll
        for (int j = 0; j < 8; ++j) {
            int oc = ocg*8 + j;
            float bv = bias[oc];
            #pragma unroll
            for (int m = 0; m < 4; ++m) {
                int ox = oxg + 8*m;
                if (ox < 26) {
                    float r = lohi(acc[j][m]) + bv;
                    g_c2[(((long)b*64 + oc)*26 + oy)*26 + ox] = fmaxf(r, 0.f);
                }
            }
        }
    }
}

// =================================================================
// conv3 v3: xs row padded to 40 f2 (80 words = 16 mod 32) -> slab offsets
// 0/16/0/16 banks => every LDS.64 exactly 2 phases. ic chunks of 8
// (4 pairs) keep smem at 26.6 KB static.
// =================================================================
__global__ __launch_bounds__(256, 2)
void conv3_kernel(const float* __restrict__ w, const float* __restrict__ bias) {
    __shared__ float2 ws[64*37];     // [oc][icp*9 + ky*3 + kx], icp<4, pad 37 (18944 B)
    __shared__ float2 xs[4*6*40];    // [icp][row 6][col 26, pad 40] (7680 B)
    const int oyp = blockIdx.x, b = blockIdx.y;
    const int oy0 = oyp * 4;
    const int tid = threadIdx.x;
    const int ocg  = tid >> 5;
    const int lane = tid & 31;
    const int slab = lane >> 3;
    const int oxg  = lane & 7;
    const int oy   = oy0 + slab;

    ULL acc[8][3];
    #pragma unroll
    for (int j = 0; j < 8; ++j)
        #pragma unroll
        for (int m = 0; m < 3; ++m) acc[j][m] = 0ULL;

    const ULL* ws_u = (const ULL*)ws;
    const ULL* xs_u = (const ULL*)xs;

    for (int ci = 0; ci < 8; ++ci) {
        const int ic0 = ci * 8;
        __syncthreads();
        for (int idx = tid; idx < 64*36; idx += 256) {
            int oc = idx / 36, r = idx % 36;
            int icp = r / 9, k = r % 9;
            int gb = oc*576 + (ic0 + 2*icp)*9 + k;
            ws[oc*37 + r] = make_float2(w[gb], w[gb + 9]);
        }
        for (int idx = tid; idx < 4*6*26; idx += 256) {
            int icp = idx / 156, rem = idx % 156;
            int row = rem / 26, col = rem % 26;
            int iy = oy0 + row;                 // oy0<=20 -> iy<=25 valid
            int gb = (((b*64 + ic0 + 2*icp)*26) + iy)*26 + col;
            xs[(icp*6 + row)*40 + col] = make_float2(g_c2[gb], g_c2[gb + 676]);
        }
        __syncthreads();

        #pragma unroll
        for (int icp = 0; icp < 4; ++icp)
        #pragma unroll
        for (int ky = 0; ky < 3; ++ky) {
            const ULL* wr = ws_u + (ocg*8)*37 + icp*9 + ky*3;
            const ULL* xr = xs_u + (icp*6 + slab + ky)*40;
            #pragma unroll
            for (int kx = 0; kx < 3; ++kx) {
                ULL wv0 = wr[0*37+kx], wv1 = wr[1*37+kx], wv2 = wr[2*37+kx], wv3 = wr[3*37+kx];
                ULL wv4 = wr[4*37+kx], wv5 = wr[5*37+kx], wv6 = wr[6*37+kx], wv7 = wr[7*37+kx];
                ULL xv0 = xr[oxg + 0 + kx], xv1 = xr[oxg + 8 + kx], xv2 = xr[oxg + 16 + kx];
                ffma2(acc[0][0], wv0, xv0); ffma2(acc[0][1], wv0, xv1); ffma2(acc[0][2], wv0, xv2);
                ffma2(acc[1][0], wv1, xv0); ffma2(acc[1][1], wv1, xv1); ffma2(acc[1][2], wv1, xv2);
                ffma2(acc[2][0], wv2, xv0); ffma2(acc[2][1], wv2, xv1); ffma2(acc[2][2], wv2, xv2);
                ffma2(acc[3][0], wv3, xv0); ffma2(acc[3][1], wv3, xv1); ffma2(acc[3][2], wv3, xv2);
                ffma2(acc[4][0], wv4, xv0); ffma2(acc[4][1], wv4, xv1); ffma2(acc[4][2], wv4, xv2);
                ffma2(acc[5][0], wv5, xv0); ffma2(acc[5][1], wv5, xv1); ffma2(acc[5][2], wv5, xv2);
                ffma2(acc[6][0], wv6, xv0); ffma2(acc[6][1], wv6, xv1); ffma2(acc[6][2], wv6, xv2);
                ffma2(acc[7][0], wv7, xv0); ffma2(acc[7][1], wv7, xv1); ffma2(acc[7][2], wv7, xv2);
            }
        }
    }
    #pragma unroll
    for (int j = 0; j < 8; ++j) {
        int oc = ocg*8 + j;
        float bv = bias[oc];
        #pragma unroll
        for (int m = 0; m < 3; ++m) {
            int ox = oxg + 8*m;
            float r = lohi(acc[j][m]) + bv;
            g_x[(long)b*36954 + oc*576 + oy*24 + ox] = fmaxf(r, 0.f);
        }
    }
}

// =================================================================
// prep: transpose w2 / w3, copy history into g_x tail
// =================================================================
__global__ void prep_kernel(const float* __restrict__ w2, const float* __restrict__ w3,
                            const float* __restrict__ hist) {
    int idx = blockIdx.x*256 + threadIdx.x;   // grid 128 -> 32768
    if (idx < 32768) { int n = idx >> 7, i = idx & 127; g_w2t[i*256 + n] = w2[idx]; }
    if (idx < 2304)  { int j = idx >> 8, i = idx & 255; g_w3t[i*9 + j]  = w3[idx]; }
    if (idx < 128*90){ int b = idx / 90, t = idx % 90;  g_x[(long)b*36954 + 36864 + t] = hist[idx]; }
}

// =================================================================
// fc1 split-K partial GEMM (unchanged)
// =================================================================
__global__ __launch_bounds__(256, 2)
void fc1_kernel(const float* __restrict__ w1) {
    __shared__ __align__(16) float As[16*132];
    __shared__ __align__(16) float Bs[16*132];
    const int blk = blockIdx.x;
    const int k0 = blk * 256;
    const int tid = threadIdx.x;
    const int tx = tid & 15, ty = tid >> 4;
    const int mrow = tid >> 1;
    const int khalf = (tid & 1) * 8;

    float c[8][8];
    #pragma unroll
    for (int i = 0; i < 8; ++i)
        #pragma unroll
        for (int j = 0; j < 8; ++j) c[i][j] = 0.f;

    for (int kt = 0; kt < 256; kt += 16) {
        #pragma unroll
        for (int i = 0; i < 8; ++i) {
            int kk = khalf + i;
            int k = k0 + kt + kk;
            float av = 0.f, bv = 0.f;
            if (k < 36954) {
                av = g_x[(long)mrow*36954 + k];
                bv = w1[(long)mrow*36954 + k];
            }
            As[kk*132 + mrow] = av;
            Bs[kk*132 + mrow] = bv;
        }
        __syncthreads();
        #pragma unroll
        for (int kk = 0; kk < 16; ++kk) {
            float4 a0 = *(const float4*)&As[kk*132 + ty*8];
            float4 a1 = *(const float4*)&As[kk*132 + ty*8 + 4];
            float4 b0 = *(const float4*)&Bs[kk*132 + tx*8];
            float4 b1 = *(const float4*)&Bs[kk*132 + tx*8 + 4];
            float a[8] = {a0.x,a0.y,a0.z,a0.w,a1.x,a1.y,a1.z,a1.w};
            float bb[8] = {b0.x,b0.y,b0.z,b0.w,b1.x,b1.y,b1.z,b1.w};
            #pragma unroll
            for (int i = 0; i < 8; ++i)
                #pragma unroll
                for (int j = 0; j < 8; ++j) c[i][j] += a[i]*bb[j];
        }
        __syncthreads();
    }
    #pragma unroll
    for (int i = 0; i < 8; ++i)
        #pragma unroll
        for (int j = 0; j < 8; ++j)
            g_part[(long)blk*16384 + (ty*8 + i)*128 + (tx*8 + j)] = c[i][j];
}

__global__ void fc1_reduce(const float* __restrict__ b1) {
    int e = blockIdx.x*512 + threadIdx.x;   // grid 32
    float s = b1[e & 127];
    #pragma unroll 4
    for (int p = 0; p < 145; ++p) s += g_part[(long)p*16384 + e];
    g_h1[e] = s;
}

// =================================================================
// LIF scan (unchanged)
// =================================================================
__global__ __launch_bounds__(256, 1)
void scan_kernel(const float* __restrict__ b2, const float* __restrict__ b3,
                 float* __restrict__ out) {
    __shared__ float h1s[128], spk1[128], spk2[256], p3[9*17];
    const int b = blockIdx.x, t = threadIdx.x;
    if (t < 128) h1s[t] = g_h1[b*128 + t];
    float mem1 = 0.f, syn1 = 0.f, mem2 = 0.f, syn2 = 0.f;
    float mem3 = 0.f, syn3 = 0.f, pot = 0.f;
    const float b2r = b2[t];
    __syncthreads();

    for (int step = 0; step < 10; ++step) {
        if (t < 128) {
            syn1 = 0.9f*syn1 + h1s[t];
            mem1 = 0.8f*mem1 + syn1;
            float s = (mem1 > 1.0f) ? 1.0f : 0.0f;
            mem1 -= s;
            spk1[t] = s;
        }
        __syncthreads();
        float h2 = b2r;
        const float* w2c = g_w2t + t;
        #pragma unroll 8
        for (int i = 0; i < 128; ++i) h2 += spk1[i] * w2c[i*256];
        syn2 = 0.9f*syn2 + h2;
        mem2 = 0.8f*mem2 + syn2;
        float s2 = (mem2 > 1.0f) ? 1.0f : 0.0f;
        mem2 -= s2;
        spk2[t] = s2;
        __syncthreads();
        if (t < 144) {
            int j = t >> 4, seg = t & 15;
            float p = 0.f;
            const float* w3c = g_w3t + j;
            #pragma unroll
            for (int i = 0; i < 16; ++i) p += spk2[seg*16 + i] * w3c[(seg*16 + i)*9];
            p3[j*17 + seg] = p;
        }
        __syncthreads();
        if (t < 9) {
            float h3 = b3[t];
            #pragma unroll
            for (int s = 0; s < 16; ++s) h3 += p3[t*17 + s];
            syn3 = 0.9f*syn3 + h3;
            mem3 = 0.8f*mem3 + syn3;
            pot += mem3;
        }
        __syncthreads();
    }
    if (t < 9) out[b*9 + t] = pot * 0.1f;
}

// =================================================================
extern "C" void kernel_launch(void* const* d_in, const int* in_sizes, int n_in,
                              void* d_out, int out_size) {
    const float* state   = (const float*)d_in[0];
    const float* history = (const float*)d_in[1];
    const float* cw1 = (const float*)d_in[2];
    const float* cb1 = (const float*)d_in[3];
    const float* cw2 = (const float*)d_in[4];
    const float* cb2 = (const float*)d_in[5];
    const float* cw3 = (const float*)d_in[6];
    const float* cb3 = (const float*)d_in[7];
    const float* w1  = (const float*)d_in[8];
    const float* b1  = (const float*)d_in[9];
    const float* w2  = (const float*)d_in[10];
    const float* b2  = (const float*)d_in[11];
    const float* w3  = (const float*)d_in[12];
    const float* b3  = (const float*)d_in[13];
    float* out = (float*)d_out;

    prep_kernel<<<128, 256>>>(w2, w3, history);
    conv1_kernel<<<dim3(55, 128), 128>>>(state, cw1, cb1);
    conv2_kernel<<<dim3(7, 128), 256>>>(cw2, cb2);
    conv3_kernel<<<dim3(6, 128), 256>>>(cw3, cb3);
    fc1_kernel<<<145, 256>>>(w1);
    fc1_reduce<<<32, 512>>>(b1);
    scan_kernel<<<128, 256>>>(b2, b3, out);
}